// round 4
// baseline (speedup 1.0000x reference)
#include <cuda_runtime.h>

// RelationalAttentionProb:
//   tab[n][c]      = x[n] . att_weight[:,c]        (c in 0..15,  rows 0..127   = w_src)
//   tab[n][16+c]   = x[n] . att_weight[:,c] (dst)  (rows 128..255 = w_dst)
//   out[e] = clip(sigmoid(tab[src_e][r_e] + tab[dst_e][16 + r_e]), 1e-5, 0.99999)

#define MAX_NODES 50000
#define D 128
#define TILE_N 64

// 50000 * 32 floats = 6.4 MB scratch table (L2-resident during kernel B)
__device__ float g_tab[MAX_NODES * 32];
// 1 = edge tensors are int64, 0 = int32 (JAX silently downcasts without x64)
__device__ int g_is64;

// ---------------------------------------------------------------------------
// Kernel 0: dtype probe. Reads first 64 entries of edge_index as int64.
// int64 data: every value in [0, N). int32 data: int64 view packs two
// consecutive indices -> value >= 2^32 unless the packed neighbor is 0
// (all-64-zero probability ~ (1/50000)^64 = never).
// ---------------------------------------------------------------------------
__global__ void relattn_detect_kernel(const void* __restrict__ ei, int N)
{
    const long long* p = (const long long*)ei;
    int ok = 1;
    for (int i = 0; i < 64; i++) {
        long long v = p[i];
        if (v < 0 || v >= (long long)N) { ok = 0; break; }
    }
    g_is64 = ok;
}

// ---------------------------------------------------------------------------
// Kernel A: skinny GEMM  (N x 128) @ (128 x 32)  -> g_tab
// Block: 256 threads as 16x16 (tx = col 0..15, ty = node-row group 0..15).
// Each thread: 4 nodes x 2 cols = 8 fp32 accumulators.
// X tile stored with a (k + 4*row) & 127 column swizzle: conflict-free reads.
// ---------------------------------------------------------------------------
__global__ __launch_bounds__(256) void relattn_gemm_kernel(
    const float* __restrict__ x,
    const float* __restrict__ att,   // (256, 16) row-major
    int N)
{
    __shared__ float Xs[TILE_N][D];   // 32 KB (swizzled columns)
    __shared__ float Ws[D][32];       // 16 KB  (total 48 KB)

    const int tid  = threadIdx.x;
    const int base = blockIdx.x * TILE_N;

    // ---- load X tile, float4, fully coalesced; swizzled store ----
    #pragma unroll
    for (int i = tid; i < TILE_N * (D / 4); i += 256) {
        int row  = i >> 5;          // 32 float4 per row
        int c4   = i & 31;
        int node = base + row;
        float4 v = make_float4(0.f, 0.f, 0.f, 0.f);
        if (node < N)
            v = reinterpret_cast<const float4*>(x)[node * (D / 4) + c4];
        int col = (c4 * 4 + 4 * row) & (D - 1);
        *reinterpret_cast<float4*>(&Xs[row][col]) = v;
    }

    // ---- combined W: col c<16 -> w_src[:,c], c>=16 -> w_dst[:,c-16] ----
    for (int i = tid; i < D * 32; i += 256) {
        int k = i >> 5;
        int c = i & 31;
        Ws[k][c] = (c < 16) ? att[k * 16 + c]
                            : att[(128 + k) * 16 + (c - 16)];
    }
    __syncthreads();

    const int tx = tid & 15;   // output column (0..15); also +16
    const int ty = tid >> 4;   // node row group (0..15)

    float acc[4][2] = {};
    #pragma unroll 8
    for (int k = 0; k < D; k++) {
        float w0 = Ws[k][tx];
        float w1 = Ws[k][tx + 16];
        #pragma unroll
        for (int i = 0; i < 4; i++) {
            int   row = ty + 16 * i;
            float xv  = Xs[row][(k + 4 * row) & (D - 1)];
            acc[i][0] = fmaf(xv, w0, acc[i][0]);
            acc[i][1] = fmaf(xv, w1, acc[i][1]);
        }
    }

    #pragma unroll
    for (int i = 0; i < 4; i++) {
        int node = base + ty + 16 * i;
        if (node < N) {
            g_tab[node * 32 + tx]      = acc[i][0];
            g_tab[node * 32 + tx + 16] = acc[i][1];
        }
    }
}

// ---------------------------------------------------------------------------
// Kernel B: per-edge gather + sigmoid + clamp. Handles int32/int64 indices
// via the probed flag (uniform branch).
// edge_index is (2, E): first E entries = src, next E = dst.
// ---------------------------------------------------------------------------
__global__ __launch_bounds__(256) void relattn_edge_kernel(
    const void* __restrict__ edge_index,
    const void* __restrict__ edge_type,
    float* __restrict__ out,
    int E)
{
    int e = blockIdx.x * 256 + threadIdx.x;
    if (e >= E) return;

    int s, d, r;
    if (g_is64) {
        const long long* ei = (const long long*)edge_index;
        const long long* et = (const long long*)edge_type;
        s = (int)ei[e];
        d = (int)ei[E + e];
        r = (int)et[e];
    } else {
        const int* ei = (const int*)edge_index;
        const int* et = (const int*)edge_type;
        s = ei[e];
        d = ei[E + e];
        r = et[e];
    }

    float sc = __ldg(&g_tab[s * 32 + r]) + __ldg(&g_tab[d * 32 + 16 + r]);
    float a  = 1.0f / (1.0f + __expf(-sc));
    out[e]   = fminf(fmaxf(a, 1e-5f), 0.99999f);
}

extern "C" void kernel_launch(void* const* d_in, const int* in_sizes, int n_in,
                              void* d_out, int out_size)
{
    const float* x   = (const float*)d_in[0];   // (N, 128) fp32
    const float* att = (const float*)d_in[1];   // (256, 16) fp32
    const void*  ei  = d_in[2];                 // (2, E) int32 or int64
    const void*  et  = d_in[3];                 // (E,)   int32 or int64

    int N = in_sizes[0] / D;
    int E = out_size;   // one float per edge -> dtype-independent

    relattn_detect_kernel<<<1, 1>>>(ei, N);
    relattn_gemm_kernel<<<(N + TILE_N - 1) / TILE_N, 256>>>(x, att, N);
    relattn_edge_kernel<<<(E + 255) / 256, 256>>>(ei, et, (float*)d_out, E);
}